// round 13
// baseline (speedup 1.0000x reference)
#include <cuda_runtime.h>
#include <stdint.h>
#include <math.h>

#define Tt 512
#define Bb 64

// ------------- static device scratch -------------
__device__ float g_xg[2][Tt*Bb*512];      // [dir][(t*64+b)*512+col]
__device__ float g_out1[Bb*Tt*256];
__device__ float g_out2[Bb*Tt*256];
__device__ float g_att[Bb*Tt*256];
__device__ float g_S[(size_t)Bb*Tt*Tt];   // gram -> softmaxed weights in place
__device__ float g_h[2][2*Bb*128];
__device__ float g_sc[Tt*Bb];
__device__ float g_a2[Bb*256];
__device__ float g_part[Bb][8][256];

__device__ __forceinline__ float sigm_fast(float x){ return __fdividef(1.f, 1.f + __expf(-x)); }
__device__ __forceinline__ float tanh_fast(float x){ return 1.f - __fdividef(2.f, __expf(2.f*x) + 1.f); }
__device__ __forceinline__ float wsum(float v){
    #pragma unroll
    for (int o=16;o;o>>=1) v += __shfl_xor_sync(0xffffffffu, v, o);
    return v;
}
__device__ __forceinline__ void fma2(unsigned long long &acc, unsigned long long a, unsigned long long b){
    asm("fma.rn.f32x2 %0, %1, %2, %0;" : "+l"(acc) : "l"(a), "l"(b));
}
__device__ __forceinline__ unsigned int tf32cvt(float x){
    unsigned int u; asm("cvt.rna.tf32.f32 %0, %1;" : "=r"(u) : "f"(x)); return u;
}
__device__ __forceinline__ void mma8(float* c, unsigned int a0,unsigned int a1,unsigned int a2,unsigned int a3,
                                     unsigned int b0,unsigned int b1){
    asm volatile("mma.sync.aligned.m16n8k8.row.col.f32.tf32.tf32.f32 "
        "{%0,%1,%2,%3}, {%4,%5,%6,%7}, {%8,%9}, {%0,%1,%2,%3};"
        : "+f"(c[0]),"+f"(c[1]),"+f"(c[2]),"+f"(c[3])
        : "r"(a0),"r"(a1),"r"(a2),"r"(a3),"r"(b0),"r"(b1));
}
__device__ __forceinline__ void mbar_wait_acq(unsigned int mbaddr, unsigned int ph){
    unsigned int done;
    asm volatile(
        "{\n\t.reg .pred p;\n\t"
        "mbarrier.try_wait.parity.acquire.cluster.shared::cta.b64 p, [%1], %2;\n\t"
        "selp.b32 %0, 1, 0, p;\n\t}"
        : "=r"(done) : "r"(mbaddr), "r"(ph) : "memory");
    while (!done){
        asm volatile(
            "{\n\t.reg .pred p;\n\t"
            "mbarrier.try_wait.parity.acquire.cluster.shared::cta.b64 p, [%1], %2, 0x989680;\n\t"
            "selp.b32 %0, 1, 0, p;\n\t}"
            : "=r"(done) : "r"(mbaddr), "r"(ph) : "memory");
    }
}

// ------------- layer-1 input projection (embedding fused), both dirs -------------
__global__ __launch_bounds__(256) void k_xg1(
    const int* __restrict__ x, const float* __restrict__ emb,
    const float* __restrict__ Wf, const float* __restrict__ bf1, const float* __restrict__ bf2,
    const float* __restrict__ Wb, const float* __restrict__ bb1, const float* __restrict__ bb2)
{
    __shared__ float wf[5120], wb[5120], bf[512], bb[512], e[10];
    int b = blockIdx.y, t0 = blockIdx.x*64, tid = threadIdx.x;
    for (int i=tid;i<5120;i+=256){ wf[i]=Wf[i]; wb[i]=Wb[i]; }
    for (int i=tid;i<512;i+=256){ bf[i]=bf1[i]+bf2[i]; bb[i]=bb1[i]+bb2[i]; }
    __syncthreads();
    for (int tl=0; tl<64; tl++){
        int t = t0+tl;
        if (tid<10) e[tid] = emb[x[b*Tt+t]*10+tid];
        __syncthreads();
        float ev[10];
        #pragma unroll
        for (int d=0;d<10;d++) ev[d]=e[d];
        for (int c=tid;c<512;c+=256){
            float af=bf[c], ab=bb[c];
            #pragma unroll
            for (int d=0;d<10;d++){ af=fmaf(ev[d],wf[c*10+d],af); ab=fmaf(ev[d],wb[c*10+d],ab); }
            g_xg[0][(t*Bb+b)*512+c]=af;
            g_xg[1][(t*Bb+b)*512+c]=ab;
        }
        __syncthreads();
    }
}

// ------------- persistent bidirectional LSTM recurrence, cluster-of-2 -------------
// Split MAC: local-half K first, then acquire-wait on peer mbarrier, then peer
// half. The producer-side arrive is EXPLICIT .release.cluster so the preceding
// st.shared::cluster h-store is ordered for the peer's acquiring consumer
// (default arrive is .release.cta — insufficient, caused R12's stale reads).
#define MACI(i) { ulonglong2 ha=h0p[i], hb=h1p[i]; \
    fma2(a0e, wp[2*(i)],   ha.x); fma2(a0o, wp[2*(i)+1], ha.y); \
    fma2(a1e, wp[2*(i)],   hb.x); fma2(a1o, wp[2*(i)+1], hb.y); }

__global__ __launch_bounds__(256,1) __cluster_dims__(2,1,1)
void k_rec(int layer, const float* __restrict__ Whh_f, const float* __restrict__ Whh_b)
{
    __shared__ __align__(16) float hsh[2][2][128];   // [phase][batch][j]
    __shared__ float gsh[2][256];                    // [batch][g*64+kl]
    __shared__ __align__(8) unsigned long long mbar[2];
    int cid = blockIdx.x>>1;
    unsigned int rank; asm("mov.u32 %0, %%cluster_ctarank;" : "=r"(rank));
    int dir = cid>>5, bpair = cid&31;
    int kb = (int)rank*64;
    int b0 = bpair*2;
    const float* Whh = dir? Whh_b : Whh_f;
    const float* xg  = g_xg[dir];
    float* out = layer? g_out2 : g_out1;
    int tid = threadIdx.x;
    int g = tid>>6, kl = tid&63;
    int grow = g*128 + kb + kl;

    unsigned long long wp[64];
    {
        const float4* wr = (const float4*)&Whh[grow*128];
        #pragma unroll
        for (int i=0;i<32;i++){
            float4 w = __ldg(&wr[i]);
            asm("mov.b64 %0, {%1,%2};" : "=l"(wp[2*i])   : "f"(w.x), "f"(w.y));
            asm("mov.b64 %0, {%1,%2};" : "=l"(wp[2*i+1]) : "f"(w.z), "f"(w.w));
        }
    }
    for (int i=tid;i<512;i+=256) ((float*)hsh)[i]=0.f;

    int cbl = tid>>6, ckl = tid&63;
    float cst = 0.f;

    unsigned int hbase;
    asm("{ .reg .u64 t; cvta.to.shared.u64 t, %1; cvt.u32.u64 %0, t; }" : "=r"(hbase) : "l"((void*)hsh));
    unsigned int mbase;
    asm("{ .reg .u64 t; cvta.to.shared.u64 t, %1; cvt.u32.u64 %0, t; }" : "=r"(mbase) : "l"((void*)mbar));
    if (tid==0){
        asm volatile("mbarrier.init.shared.b64 [%0], %1;" :: "r"(mbase),   "r"(128u) : "memory");
        asm volatile("mbarrier.init.shared.b64 [%0], %1;" :: "r"(mbase+8), "r"(128u) : "memory");
    }
    unsigned int peer_hbase, peer_mbase;
    asm("mapa.shared::cluster.u32 %0, %1, %2;" : "=r"(peer_hbase) : "r"(hbase), "r"(rank^1u));
    asm("mapa.shared::cluster.u32 %0, %1, %2;" : "=r"(peer_mbase) : "r"(mbase), "r"(rank^1u));

    __syncthreads();
    asm volatile("barrier.cluster.arrive.aligned;" ::: "memory");
    asm volatile("barrier.cluster.wait.aligned;"   ::: "memory");

    int tI = dir? 511 : 0;
    float xgc0 = __ldg(&xg[(tI*Bb + b0  )*512 + grow]);
    float xgc1 = __ldg(&xg[(tI*Bb + b0+1)*512 + grow]);
    int p = 0;
    int par0 = 0, par1 = 0;

    for (int s=0; s<Tt; s++){
        int t = dir ? (511-s) : s;
        unsigned long long a0e=0ull, a0o=0ull, a1e=0ull, a1o=0ull;
        const ulonglong2* h0p = (const ulonglong2*)hsh[p][0];
        const ulonglong2* h1p = (const ulonglong2*)hsh[p][1];
        if (rank==0){
            #pragma unroll
            for (int i=0;i<16;i++) MACI(i)           // local half: j 0..63
            if (s>0){
                int ph = p? par1 : par0;
                mbar_wait_acq(mbase + (unsigned)p*8u, (unsigned)ph);
                if (p) par1^=1; else par0^=1;
            }
            #pragma unroll
            for (int i=16;i<32;i++) MACI(i)          // peer half: j 64..127
        } else {
            #pragma unroll
            for (int i=16;i<32;i++) MACI(i)          // local half: j 64..127
            if (s>0){
                int ph = p? par1 : par0;
                mbar_wait_acq(mbase + (unsigned)p*8u, (unsigned)ph);
                if (p) par1^=1; else par0^=1;
            }
            #pragma unroll
            for (int i=0;i<16;i++) MACI(i)           // peer half: j 0..63
        }
        float u0,v0,u1,v1,u2,v2,u3,v3;
        asm("mov.b64 {%0,%1}, %2;" : "=f"(u0),"=f"(v0) : "l"(a0e));
        asm("mov.b64 {%0,%1}, %2;" : "=f"(u1),"=f"(v1) : "l"(a0o));
        asm("mov.b64 {%0,%1}, %2;" : "=f"(u2),"=f"(v2) : "l"(a1e));
        asm("mov.b64 {%0,%1}, %2;" : "=f"(u3),"=f"(v3) : "l"(a1o));
        gsh[0][tid] = (u0+v0) + (u1+v1) + xgc0;
        gsh[1][tid] = (u2+v2) + (u3+v3) + xgc1;
        if (s<511){
            int tn = dir? (510-s) : (s+1);
            xgc0 = __ldg(&xg[(tn*Bb + b0  )*512 + grow]);
            xgc1 = __ldg(&xg[(tn*Bb + b0+1)*512 + grow]);
        }
        __syncthreads();
        int np = p^1;
        if (tid<128){
            float gi=gsh[cbl][ckl], gf=gsh[cbl][64+ckl], gg=gsh[cbl][128+ckl], go=gsh[cbl][192+ckl];
            cst = sigm_fast(gf)*cst + sigm_fast(gi)*tanh_fast(gg);
            float hv = sigm_fast(go)*tanh_fast(cst);
            int k = kb + ckl;
            out[((b0+cbl)*Tt + t)*256 + dir*128 + k] = hv;
            if (s==511){
                g_h[layer][dir*Bb*128 + (b0+cbl)*128 + k] = hv;
            } else {
                hsh[np][cbl][k] = hv;
                unsigned int off = (unsigned int)(((np*2+cbl)*128 + k)*4);
                asm volatile("st.shared::cluster.f32 [%0], %1;" :: "r"(peer_hbase+off), "f"(hv) : "memory");
                asm volatile("mbarrier.arrive.release.cluster.shared::cluster.b64 _, [%0];" :: "r"(peer_mbase + (unsigned)np*8u) : "memory");
            }
        }
        __syncthreads();
        p ^= 1;
    }
    asm volatile("barrier.cluster.arrive.aligned;" ::: "memory");
    asm volatile("barrier.cluster.wait.aligned;"   ::: "memory");
}

// ------------- prefix gram S[b][i][t]=dot/max(i,1), tf32 mma, 64x64 tiles -------------
__global__ __launch_bounds__(256) void k_gram(){
    int ti=blockIdx.x, tj=blockIdx.y, b=blockIdx.z;
    if (tj>ti) return;
    __shared__ unsigned int As[64*36], Bs[64*36];
    const float* O = g_out1 + (size_t)b*Tt*256;
    int i0=ti*64, t0=tj*64, tid=threadIdx.x;
    int lane=tid&31, wid=tid>>5, g=lane>>2, tg=lane&3;
    int wm=wid>>1, wn=wid&1;
    float acc[4][4]={};
    for (int kc=0;kc<256;kc+=32){
        #pragma unroll
        for (int e=0;e<2;e++){
            int idx=tid+e*256; int m=idx>>3, k4=idx&7;
            float4 va=*(const float4*)&O[(i0+m)*256+kc+k4*4];
            float4 vb=*(const float4*)&O[(t0+m)*256+kc+k4*4];
            int base=m*36+k4*4;
            As[base]=tf32cvt(va.x); As[base+1]=tf32cvt(va.y); As[base+2]=tf32cvt(va.z); As[base+3]=tf32cvt(va.w);
            Bs[base]=tf32cvt(vb.x); Bs[base+1]=tf32cvt(vb.y); Bs[base+2]=tf32cvt(vb.z); Bs[base+3]=tf32cvt(vb.w);
        }
        __syncthreads();
        #pragma unroll
        for (int ks=0;ks<4;ks++){
            int ko=ks*8;
            unsigned int a0=As[(wm*16+g)*36+ko+tg],   a1=As[(wm*16+g+8)*36+ko+tg];
            unsigned int a2=As[(wm*16+g)*36+ko+tg+4], a3=As[(wm*16+g+8)*36+ko+tg+4];
            #pragma unroll
            for (int nt=0;nt<4;nt++){
                int no=wn*32+nt*8;
                unsigned int b0=Bs[(no+g)*36+ko+tg], b1=Bs[(no+g)*36+ko+tg+4];
                mma8(acc[nt], a0,a1,a2,a3,b0,b1);
            }
        }
        __syncthreads();
    }
    int i_a = i0 + wm*16 + g, i_b = i_a + 8;
    float sa = 1.f/(float)(i_a>0?i_a:1), sb = 1.f/(float)(i_b>0?i_b:1);
    #pragma unroll
    for (int nt=0;nt<4;nt++){
        int col = t0 + wn*32 + nt*8 + tg*2;
        float2 r0; r0.x=acc[nt][0]*sa; r0.y=acc[nt][1]*sa;
        float2 r1; r1.x=acc[nt][2]*sb; r1.y=acc[nt][3]*sb;
        *(float2*)&g_S[((size_t)b*Tt+i_a)*Tt+col]=r0;
        *(float2*)&g_S[((size_t)b*Tt+i_b)*Tt+col]=r1;
    }
}

// ------------- softmax over batch per (i,t), t<i -------------
__global__ void k_bsoft(){
    int i=blockIdx.x, t=threadIdx.x;
    if (t>=i) return;
    size_t base=(size_t)i*Tt+t;
    float v[64], m=-1e30f;
    #pragma unroll
    for (int b=0;b<64;b++){ v[b]=g_S[(size_t)b*Tt*Tt+base]; m=fmaxf(m,v[b]); }
    float s=0.f;
    #pragma unroll
    for (int b=0;b<64;b++){ v[b]=__expf(v[b]-m); s+=v[b]; }
    float inv=__fdividef(1.f,s);
    #pragma unroll
    for (int b=0;b<64;b++) g_S[(size_t)b*Tt*Tt+base]=v[b]*inv;
}

// ------------- att[b][i][:] = sum_{t<i} W[b,i,t]*out1[b,t,:], tf32 mma -------------
__global__ __launch_bounds__(256) void k_apply(){
    int i0=blockIdx.x*64, d0=blockIdx.y*64, b=blockIdx.z;
    __shared__ unsigned int As[64*36], Bs[64*36];
    const float* O=g_out1+(size_t)b*Tt*256;
    const float* W=g_S+(size_t)b*Tt*Tt;
    int tid=threadIdx.x;
    int lane=tid&31, wid=tid>>5, g=lane>>2, tg=lane&3;
    int wm=wid>>1, wn=wid&1;
    float acc[4][4]={};
    int kmax=i0+64;
    for (int tk=0;tk<kmax;tk+=32){
        #pragma unroll
        for (int e=0;e<2;e++){
            int idx=tid+e*256; int m=idx>>3, k4=idx&7;
            int i_r = i0+m;
            int tbase = tk+k4*4;
            float4 va=*(const float4*)&W[(size_t)i_r*Tt + tbase];
            if (tbase+0 >= i_r) va.x=0.f;
            if (tbase+1 >= i_r) va.y=0.f;
            if (tbase+2 >= i_r) va.z=0.f;
            if (tbase+3 >= i_r) va.w=0.f;
            int base=m*36+k4*4;
            As[base]=tf32cvt(va.x); As[base+1]=tf32cvt(va.y); As[base+2]=tf32cvt(va.z); As[base+3]=tf32cvt(va.w);
        }
        #pragma unroll
        for (int e=0;e<2;e++){
            int idx=tid+e*256; int k=idx&31, n4=idx>>5;
            float4 v=*(const float4*)&O[(tk+k)*256 + d0+n4*4];
            Bs[(n4*4  )*36+k]=tf32cvt(v.x);
            Bs[(n4*4+1)*36+k]=tf32cvt(v.y);
            Bs[(n4*4+2)*36+k]=tf32cvt(v.z);
            Bs[(n4*4+3)*36+k]=tf32cvt(v.w);
        }
        __syncthreads();
        #pragma unroll
        for (int ks=0;ks<4;ks++){
            int ko=ks*8;
            unsigned int a0=As[(wm*16+g)*36+ko+tg],   a1=As[(wm*16+g+8)*36+ko+tg];
            unsigned int a2=As[(wm*16+g)*36+ko+tg+4], a3=As[(wm*16+g+8)*36+ko+tg+4];
            #pragma unroll
            for (int nt=0;nt<4;nt++){
                int no=wn*32+nt*8;
                unsigned int b0=Bs[(no+g)*36+ko+tg], b1=Bs[(no+g)*36+ko+tg+4];
                mma8(acc[nt], a0,a1,a2,a3,b0,b1);
            }
        }
        __syncthreads();
    }
    float* A=g_att+(size_t)b*Tt*256;
    int i_a = i0 + wm*16 + g, i_b = i_a + 8;
    #pragma unroll
    for (int nt=0;nt<4;nt++){
        int col = d0 + wn*32 + nt*8 + tg*2;
        float2 r0; r0.x=acc[nt][0]; r0.y=acc[nt][1];
        float2 r1; r1.x=acc[nt][2]; r1.y=acc[nt][3];
        *(float2*)&A[(size_t)i_a*256+col]=r0;
        *(float2*)&A[(size_t)i_b*256+col]=r1;
    }
}

// ------------- full attention: scores + softmax over batch (per t) -------------
__global__ void k_score(int layer){
    const float* O = layer? g_out2 : g_out1;
    const float* h = g_h[layer];
    int t=blockIdx.x, tid=threadIdx.x, w=tid>>5, lane=tid&31;
    __shared__ float sc[64];
    for (int j=0;j<8;j++){
        int b=w*8+j;
        const float* o=O+((size_t)b*Tt+t)*256;
        const float* hb=h+b*256;
        float a=0.f;
        for (int k=lane;k<256;k+=32) a=fmaf(o[k],hb[k],a);
        a=wsum(a);
        if (lane==0) sc[b]=a*(1.f/512.f);
    }
    __syncthreads();
    if (tid<32){
        float v0=sc[tid], v1=sc[tid+32];
        float m=fmaxf(v0,v1);
        #pragma unroll
        for (int o=16;o;o>>=1) m=fmaxf(m,__shfl_xor_sync(0xffffffffu,m,o));
        float e0=__expf(v0-m), e1=__expf(v1-m);
        float s=e0+e1;
        s=wsum(s);
        float inv=__fdividef(1.f,s);
        g_sc[t*64+tid]=e0*inv;
        g_sc[t*64+tid+32]=e1*inv;
    }
}

__global__ void k_fsum1(int layer){
    const float* O = layer? g_out2 : g_out1;
    int b=blockIdx.x, tc=blockIdx.y, d=threadIdx.x;
    const float* o=O+(size_t)b*Tt*256;
    float a=0.f;
    int t0=tc*64;
    for (int t=t0;t<t0+64;t++) a=fmaf(g_sc[t*64+b], o[t*256+d], a);
    g_part[b][tc][d]=a;
}
__global__ void k_fsum2(int layer){
    int b=blockIdx.x, d=threadIdx.x;
    float a=0.f;
    #pragma unroll
    for (int c=0;c<8;c++) a+=g_part[b][c][d];
    if (layer==0) g_att[((size_t)b*Tt+511)*256+d]=a;
    else          g_a2[b*256+d]=a;
}

// ------------- layer-2 input projection GEMM: xg2 = att @ Wih2^T + bias, tf32 mma -------------
__global__ __launch_bounds__(256) void k_xg2(
    const float* __restrict__ Wf, const float* __restrict__ bf1, const float* __restrict__ bf2,
    const float* __restrict__ Wb, const float* __restrict__ bb1, const float* __restrict__ bb2)
{
    int t0=blockIdx.x*64, col0=blockIdx.y*64;
    int z=blockIdx.z; int b=z>>1, dir=z&1;
    const float* W2 = dir? Wb : Wf;
    __shared__ unsigned int As[64*36], Bs[64*36];
    __shared__ float bsh[64];
    int tid=threadIdx.x;
    int lane=tid&31, wid=tid>>5, g=lane>>2, tg=lane&3;
    int wm=wid>>1, wn=wid&1;
    if (tid<64) bsh[tid] = dir? (bb1[col0+tid]+bb2[col0+tid]) : (bf1[col0+tid]+bf2[col0+tid]);
    const float* A = g_att + (size_t)b*Tt*256;
    float acc[4][4]={};
    for (int kc=0;kc<256;kc+=32){
        #pragma unroll
        for (int e=0;e<2;e++){
            int idx=tid+e*256; int m=idx>>3, k4=idx&7;
            float4 va=*(const float4*)&A[(t0+m)*256+kc+k4*4];
            float4 vb=*(const float4*)&W2[(col0+m)*256+kc+k4*4];
            int base=m*36+k4*4;
            As[base]=tf32cvt(va.x); As[base+1]=tf32cvt(va.y); As[base+2]=tf32cvt(va.z); As[base+3]=tf32cvt(va.w);
            Bs[base]=tf32cvt(vb.x); Bs[base+1]=tf32cvt(vb.y); Bs[base+2]=tf32cvt(vb.z); Bs[base+3]=tf32cvt(vb.w);
        }
        __syncthreads();
        #pragma unroll
        for (int ks=0;ks<4;ks++){
            int ko=ks*8;
            unsigned int a0=As[(wm*16+g)*36+ko+tg],   a1=As[(wm*16+g+8)*36+ko+tg];
            unsigned int a2=As[(wm*16+g)*36+ko+tg+4], a3=As[(wm*16+g+8)*36+ko+tg+4];
            #pragma unroll
            for (int nt=0;nt<4;nt++){
                int no=wn*32+nt*8;
                unsigned int b0=Bs[(no+g)*36+ko+tg], b1=Bs[(no+g)*36+ko+tg+4];
                mma8(acc[nt], a0,a1,a2,a3,b0,b1);
            }
        }
        __syncthreads();
    }
    int t_a = t0 + wm*16 + g, t_b = t_a + 8;
    #pragma unroll
    for (int nt=0;nt<4;nt++){
        int cl = wn*32 + nt*8 + tg*2;
        float2 r0; r0.x=acc[nt][0]+bsh[cl]; r0.y=acc[nt][1]+bsh[cl+1];
        float2 r1; r1.x=acc[nt][2]+bsh[cl]; r1.y=acc[nt][3]+bsh[cl+1];
        *(float2*)&g_xg[dir][(t_a*Bb+b)*512 + col0 + cl] = r0;
        *(float2*)&g_xg[dir][(t_b*Bb+b)*512 + col0 + cl] = r1;
    }
}

__global__ void k_final(const float* __restrict__ W, const float* __restrict__ bb, float* out){
    __shared__ float w[256];
    int tid=threadIdx.x;
    for (int i=tid;i<256;i+=64) w[i]=W[i];
    __syncthreads();
    float a=bb[0];
    for (int k=0;k<256;k++) a=fmaf(g_a2[tid*256+k],w[k],a);
    out[tid]=sigm_fast(a);
}

extern "C" void kernel_launch(void* const* d_in, const int* in_sizes, int n_in,
                              void* d_out, int out_size)
{
    const int*   x   = (const int*)  d_in[0];
    const float* emb = (const float*)d_in[1];
    const float* l1Wihf=(const float*)d_in[2],  *l1Whhf=(const float*)d_in[3];
    const float* l1bihf=(const float*)d_in[4],  *l1bhhf=(const float*)d_in[5];
    const float* l1Wihb=(const float*)d_in[6],  *l1Whhb=(const float*)d_in[7];
    const float* l1bihb=(const float*)d_in[8],  *l1bhhb=(const float*)d_in[9];
    const float* l2Wihf=(const float*)d_in[10], *l2Whhf=(const float*)d_in[11];
    const float* l2bihf=(const float*)d_in[12], *l2bhhf=(const float*)d_in[13];
    const float* l2Wihb=(const float*)d_in[14], *l2Whhb=(const float*)d_in[15];
    const float* l2bihb=(const float*)d_in[16], *l2bhhb=(const float*)d_in[17];
    const float* linW=(const float*)d_in[18],   *linb=(const float*)d_in[19];
    float* out=(float*)d_out;

    k_xg1<<<dim3(8,64),256>>>(x,emb,l1Wihf,l1bihf,l1bhhf,l1Wihb,l1bihb,l1bhhb);
    k_rec<<<128,256>>>(0,l1Whhf,l1Whhb);
    k_gram<<<dim3(8,8,64),256>>>();
    k_bsoft<<<512,512>>>();
    k_apply<<<dim3(8,4,64),256>>>();
    k_score<<<512,256>>>(0);
    k_fsum1<<<dim3(64,8),256>>>(0);
    k_fsum2<<<64,256>>>(0);
    k_xg2<<<dim3(8,8,128),256>>>(l2Wihf,l2bihf,l2bhhf,l2Wihb,l2bihb,l2bhhb);
    k_rec<<<128,256>>>(1,l2Whhf,l2Whhb);
    k_score<<<512,256>>>(1);
    k_fsum1<<<dim3(64,8),256>>>(1);
    k_fsum2<<<64,256>>>(1);
    k_final<<<1,64>>>(linW,linb,out);
}

// round 14
// speedup vs baseline: 1.0964x; 1.0964x over previous
#include <cuda_runtime.h>
#include <stdint.h>
#include <math.h>

#define Tt 512
#define Bb 64

// ------------- static device scratch -------------
__device__ float g_xg[2][Tt*Bb*512];      // [dir][(t*64+b)*512+col]
__device__ float g_out1[Bb*Tt*256];
__device__ float g_out2[Bb*Tt*256];
__device__ float g_att[Bb*Tt*256];
__device__ float g_S[(size_t)Bb*Tt*Tt];   // gram -> softmaxed weights in place
__device__ float g_h[2][2*Bb*128];
__device__ float g_sc[Tt*Bb];
__device__ float g_a2[Bb*256];
__device__ float g_part[Bb][8][256];

__device__ __forceinline__ float sigm_fast(float x){ return __fdividef(1.f, 1.f + __expf(-x)); }
__device__ __forceinline__ float tanh_fast(float x){ return 1.f - __fdividef(2.f, __expf(2.f*x) + 1.f); }
__device__ __forceinline__ float wsum(float v){
    #pragma unroll
    for (int o=16;o;o>>=1) v += __shfl_xor_sync(0xffffffffu, v, o);
    return v;
}
__device__ __forceinline__ void fma2(unsigned long long &acc, unsigned long long a, unsigned long long b){
    asm("fma.rn.f32x2 %0, %1, %2, %0;" : "+l"(acc) : "l"(a), "l"(b));
}
__device__ __forceinline__ unsigned int tf32cvt(float x){
    unsigned int u; asm("cvt.rna.tf32.f32 %0, %1;" : "=r"(u) : "f"(x)); return u;
}
__device__ __forceinline__ void mma8(float* c, unsigned int a0,unsigned int a1,unsigned int a2,unsigned int a3,
                                     unsigned int b0,unsigned int b1){
    asm volatile("mma.sync.aligned.m16n8k8.row.col.f32.tf32.tf32.f32 "
        "{%0,%1,%2,%3}, {%4,%5,%6,%7}, {%8,%9}, {%0,%1,%2,%3};"
        : "+f"(c[0]),"+f"(c[1]),"+f"(c[2]),"+f"(c[3])
        : "r"(a0),"r"(a1),"r"(a2),"r"(a3),"r"(b0),"r"(b1));
}
__device__ __forceinline__ void mbar_wait_acq(unsigned int mbaddr, unsigned int ph){
    unsigned int done;
    asm volatile(
        "{\n\t.reg .pred p;\n\t"
        "mbarrier.try_wait.parity.acquire.cluster.shared::cta.b64 p, [%1], %2;\n\t"
        "selp.b32 %0, 1, 0, p;\n\t}"
        : "=r"(done) : "r"(mbaddr), "r"(ph) : "memory");
    while (!done){
        asm volatile(
            "{\n\t.reg .pred p;\n\t"
            "mbarrier.try_wait.parity.acquire.cluster.shared::cta.b64 p, [%1], %2, 0x989680;\n\t"
            "selp.b32 %0, 1, 0, p;\n\t}"
            : "=r"(done) : "r"(mbaddr), "r"(ph) : "memory");
    }
}

// ------------- layer-1 input projection (embedding fused), both dirs -------------
__global__ __launch_bounds__(256) void k_xg1(
    const int* __restrict__ x, const float* __restrict__ emb,
    const float* __restrict__ Wf, const float* __restrict__ bf1, const float* __restrict__ bf2,
    const float* __restrict__ Wb, const float* __restrict__ bb1, const float* __restrict__ bb2)
{
    __shared__ float wf[5120], wb[5120], bf[512], bb[512], e[10];
    int b = blockIdx.y, t0 = blockIdx.x*64, tid = threadIdx.x;
    for (int i=tid;i<5120;i+=256){ wf[i]=Wf[i]; wb[i]=Wb[i]; }
    for (int i=tid;i<512;i+=256){ bf[i]=bf1[i]+bf2[i]; bb[i]=bb1[i]+bb2[i]; }
    __syncthreads();
    for (int tl=0; tl<64; tl++){
        int t = t0+tl;
        if (tid<10) e[tid] = emb[x[b*Tt+t]*10+tid];
        __syncthreads();
        float ev[10];
        #pragma unroll
        for (int d=0;d<10;d++) ev[d]=e[d];
        for (int c=tid;c<512;c+=256){
            float af=bf[c], ab=bb[c];
            #pragma unroll
            for (int d=0;d<10;d++){ af=fmaf(ev[d],wf[c*10+d],af); ab=fmaf(ev[d],wb[c*10+d],ab); }
            g_xg[0][(t*Bb+b)*512+c]=af;
            g_xg[1][(t*Bb+b)*512+c]=ab;
        }
        __syncthreads();
    }
}

// ------------- persistent bidirectional LSTM recurrence, cluster-of-2 -------------
// Split MAC (local half -> acquire-wait -> peer half) with SINGLE-COMMITTER
// ordering: cell threads do plain DSMEM h-stores; after __syncthreads, tid 0
// issues one cumulative fence.acq_rel.cluster + one plain arrive (count=1).
// Sound (fence is cumulative over the CTA's prior stores) and cheap (1 fence +
// 1 arrive per CTA per step, off the other 255 threads' critical path).
#define MACI(i) { ulonglong2 ha=h0p[i], hb=h1p[i]; \
    fma2(a0e, wp[2*(i)],   ha.x); fma2(a0o, wp[2*(i)+1], ha.y); \
    fma2(a1e, wp[2*(i)],   hb.x); fma2(a1o, wp[2*(i)+1], hb.y); }

__global__ __launch_bounds__(256,1) __cluster_dims__(2,1,1)
void k_rec(int layer, const float* __restrict__ Whh_f, const float* __restrict__ Whh_b)
{
    __shared__ __align__(16) float hsh[2][2][128];   // [phase][batch][j]
    __shared__ float gsh[2][256];                    // [batch][g*64+kl]
    __shared__ __align__(8) unsigned long long mbar[2];
    int cid = blockIdx.x>>1;
    unsigned int rank; asm("mov.u32 %0, %%cluster_ctarank;" : "=r"(rank));
    int dir = cid>>5, bpair = cid&31;
    int kb = (int)rank*64;
    int b0 = bpair*2;
    const float* Whh = dir? Whh_b : Whh_f;
    const float* xg  = g_xg[dir];
    float* out = layer? g_out2 : g_out1;
    int tid = threadIdx.x;
    int g = tid>>6, kl = tid&63;
    int grow = g*128 + kb + kl;

    unsigned long long wp[64];
    {
        const float4* wr = (const float4*)&Whh[grow*128];
        #pragma unroll
        for (int i=0;i<32;i++){
            float4 w = __ldg(&wr[i]);
            asm("mov.b64 %0, {%1,%2};" : "=l"(wp[2*i])   : "f"(w.x), "f"(w.y));
            asm("mov.b64 %0, {%1,%2};" : "=l"(wp[2*i+1]) : "f"(w.z), "f"(w.w));
        }
    }
    for (int i=tid;i<512;i+=256) ((float*)hsh)[i]=0.f;

    int cbl = tid>>6, ckl = tid&63;
    float cst = 0.f;

    unsigned int hbase;
    asm("{ .reg .u64 t; cvta.to.shared.u64 t, %1; cvt.u32.u64 %0, t; }" : "=r"(hbase) : "l"((void*)hsh));
    unsigned int mbase;
    asm("{ .reg .u64 t; cvta.to.shared.u64 t, %1; cvt.u32.u64 %0, t; }" : "=r"(mbase) : "l"((void*)mbar));
    if (tid==0){
        asm volatile("mbarrier.init.shared.b64 [%0], %1;" :: "r"(mbase),   "r"(1u) : "memory");
        asm volatile("mbarrier.init.shared.b64 [%0], %1;" :: "r"(mbase+8), "r"(1u) : "memory");
    }
    unsigned int peer_hbase, peer_mbase;
    asm("mapa.shared::cluster.u32 %0, %1, %2;" : "=r"(peer_hbase) : "r"(hbase), "r"(rank^1u));
    asm("mapa.shared::cluster.u32 %0, %1, %2;" : "=r"(peer_mbase) : "r"(mbase), "r"(rank^1u));

    __syncthreads();
    asm volatile("barrier.cluster.arrive.aligned;" ::: "memory");
    asm volatile("barrier.cluster.wait.aligned;"   ::: "memory");

    int tI = dir? 511 : 0;
    float xgc0 = __ldg(&xg[(tI*Bb + b0  )*512 + grow]);
    float xgc1 = __ldg(&xg[(tI*Bb + b0+1)*512 + grow]);
    int p = 0;
    int par0 = 0, par1 = 0;

    for (int s=0; s<Tt; s++){
        int t = dir ? (511-s) : s;
        unsigned long long a0e=0ull, a0o=0ull, a1e=0ull, a1o=0ull;
        const ulonglong2* h0p = (const ulonglong2*)hsh[p][0];
        const ulonglong2* h1p = (const ulonglong2*)hsh[p][1];
        if (rank==0){
            #pragma unroll
            for (int i=0;i<16;i++) MACI(i)           // local half: j 0..63
            if (s>0){
                int ph = p? par1 : par0;
                mbar_wait_acq(mbase + (unsigned)p*8u, (unsigned)ph);
                if (p) par1^=1; else par0^=1;
            }
            #pragma unroll
            for (int i=16;i<32;i++) MACI(i)          // peer half: j 64..127
        } else {
            #pragma unroll
            for (int i=16;i<32;i++) MACI(i)          // local half: j 64..127
            if (s>0){
                int ph = p? par1 : par0;
                mbar_wait_acq(mbase + (unsigned)p*8u, (unsigned)ph);
                if (p) par1^=1; else par0^=1;
            }
            #pragma unroll
            for (int i=0;i<16;i++) MACI(i)           // peer half: j 0..63
        }
        float u0,v0,u1,v1,u2,v2,u3,v3;
        asm("mov.b64 {%0,%1}, %2;" : "=f"(u0),"=f"(v0) : "l"(a0e));
        asm("mov.b64 {%0,%1}, %2;" : "=f"(u1),"=f"(v1) : "l"(a0o));
        asm("mov.b64 {%0,%1}, %2;" : "=f"(u2),"=f"(v2) : "l"(a1e));
        asm("mov.b64 {%0,%1}, %2;" : "=f"(u3),"=f"(v3) : "l"(a1o));
        gsh[0][tid] = (u0+v0) + (u1+v1) + xgc0;
        gsh[1][tid] = (u2+v2) + (u3+v3) + xgc1;
        if (s<511){
            int tn = dir? (510-s) : (s+1);
            xgc0 = __ldg(&xg[(tn*Bb + b0  )*512 + grow]);
            xgc1 = __ldg(&xg[(tn*Bb + b0+1)*512 + grow]);
        }
        __syncthreads();
        int np = p^1;
        if (tid<128){
            float gi=gsh[cbl][ckl], gf=gsh[cbl][64+ckl], gg=gsh[cbl][128+ckl], go=gsh[cbl][192+ckl];
            cst = sigm_fast(gf)*cst + sigm_fast(gi)*tanh_fast(gg);
            float hv = sigm_fast(go)*tanh_fast(cst);
            int k = kb + ckl;
            out[((b0+cbl)*Tt + t)*256 + dir*128 + k] = hv;
            if (s==511){
                g_h[layer][dir*Bb*128 + (b0+cbl)*128 + k] = hv;
            } else {
                hsh[np][cbl][k] = hv;
                unsigned int off = (unsigned int)(((np*2+cbl)*128 + k)*4);
                asm volatile("st.shared::cluster.f32 [%0], %1;" :: "r"(peer_hbase+off), "f"(hv) : "memory");
            }
        }
        __syncthreads();
        if (tid==0 && s<511){
            asm volatile("fence.acq_rel.cluster;" ::: "memory");
            asm volatile("mbarrier.arrive.shared::cluster.b64 _, [%0];" :: "r"(peer_mbase + (unsigned)np*8u) : "memory");
        }
        p ^= 1;
    }
    asm volatile("barrier.cluster.arrive.aligned;" ::: "memory");
    asm volatile("barrier.cluster.wait.aligned;"   ::: "memory");
}

// ------------- prefix gram S[b][i][t]=dot/max(i,1), tf32 mma, 64x64 tiles -------------
__global__ __launch_bounds__(256) void k_gram(){
    int ti=blockIdx.x, tj=blockIdx.y, b=blockIdx.z;
    if (tj>ti) return;
    __shared__ unsigned int As[64*36], Bs[64*36];
    const float* O = g_out1 + (size_t)b*Tt*256;
    int i0=ti*64, t0=tj*64, tid=threadIdx.x;
    int lane=tid&31, wid=tid>>5, g=lane>>2, tg=lane&3;
    int wm=wid>>1, wn=wid&1;
    float acc[4][4]={};
    for (int kc=0;kc<256;kc+=32){
        #pragma unroll
        for (int e=0;e<2;e++){
            int idx=tid+e*256; int m=idx>>3, k4=idx&7;
            float4 va=*(const float4*)&O[(i0+m)*256+kc+k4*4];
            float4 vb=*(const float4*)&O[(t0+m)*256+kc+k4*4];
            int base=m*36+k4*4;
            As[base]=tf32cvt(va.x); As[base+1]=tf32cvt(va.y); As[base+2]=tf32cvt(va.z); As[base+3]=tf32cvt(va.w);
            Bs[base]=tf32cvt(vb.x); Bs[base+1]=tf32cvt(vb.y); Bs[base+2]=tf32cvt(vb.z); Bs[base+3]=tf32cvt(vb.w);
        }
        __syncthreads();
        #pragma unroll
        for (int ks=0;ks<4;ks++){
            int ko=ks*8;
            unsigned int a0=As[(wm*16+g)*36+ko+tg],   a1=As[(wm*16+g+8)*36+ko+tg];
            unsigned int a2=As[(wm*16+g)*36+ko+tg+4], a3=As[(wm*16+g+8)*36+ko+tg+4];
            #pragma unroll
            for (int nt=0;nt<4;nt++){
                int no=wn*32+nt*8;
                unsigned int b0=Bs[(no+g)*36+ko+tg], b1=Bs[(no+g)*36+ko+tg+4];
                mma8(acc[nt], a0,a1,a2,a3,b0,b1);
            }
        }
        __syncthreads();
    }
    int i_a = i0 + wm*16 + g, i_b = i_a + 8;
    float sa = 1.f/(float)(i_a>0?i_a:1), sb = 1.f/(float)(i_b>0?i_b:1);
    #pragma unroll
    for (int nt=0;nt<4;nt++){
        int col = t0 + wn*32 + nt*8 + tg*2;
        float2 r0; r0.x=acc[nt][0]*sa; r0.y=acc[nt][1]*sa;
        float2 r1; r1.x=acc[nt][2]*sb; r1.y=acc[nt][3]*sb;
        *(float2*)&g_S[((size_t)b*Tt+i_a)*Tt+col]=r0;
        *(float2*)&g_S[((size_t)b*Tt+i_b)*Tt+col]=r1;
    }
}

// ------------- softmax over batch per (i,t), t<i -------------
__global__ void k_bsoft(){
    int i=blockIdx.x, t=threadIdx.x;
    if (t>=i) return;
    size_t base=(size_t)i*Tt+t;
    float v[64], m=-1e30f;
    #pragma unroll
    for (int b=0;b<64;b++){ v[b]=g_S[(size_t)b*Tt*Tt+base]; m=fmaxf(m,v[b]); }
    float s=0.f;
    #pragma unroll
    for (int b=0;b<64;b++){ v[b]=__expf(v[b]-m); s+=v[b]; }
    float inv=__fdividef(1.f,s);
    #pragma unroll
    for (int b=0;b<64;b++) g_S[(size_t)b*Tt*Tt+base]=v[b]*inv;
}

// ------------- att[b][i][:] = sum_{t<i} W[b,i,t]*out1[b,t,:], tf32 mma -------------
__global__ __launch_bounds__(256) void k_apply(){
    int i0=blockIdx.x*64, d0=blockIdx.y*64, b=blockIdx.z;
    __shared__ unsigned int As[64*36], Bs[64*36];
    const float* O=g_out1+(size_t)b*Tt*256;
    const float* W=g_S+(size_t)b*Tt*Tt;
    int tid=threadIdx.x;
    int lane=tid&31, wid=tid>>5, g=lane>>2, tg=lane&3;
    int wm=wid>>1, wn=wid&1;
    float acc[4][4]={};
    int kmax=i0+64;
    for (int tk=0;tk<kmax;tk+=32){
        #pragma unroll
        for (int e=0;e<2;e++){
            int idx=tid+e*256; int m=idx>>3, k4=idx&7;
            int i_r = i0+m;
            int tbase = tk+k4*4;
            float4 va=*(const float4*)&W[(size_t)i_r*Tt + tbase];
            if (tbase+0 >= i_r) va.x=0.f;
            if (tbase+1 >= i_r) va.y=0.f;
            if (tbase+2 >= i_r) va.z=0.f;
            if (tbase+3 >= i_r) va.w=0.f;
            int base=m*36+k4*4;
            As[base]=tf32cvt(va.x); As[base+1]=tf32cvt(va.y); As[base+2]=tf32cvt(va.z); As[base+3]=tf32cvt(va.w);
        }
        #pragma unroll
        for (int e=0;e<2;e++){
            int idx=tid+e*256; int k=idx&31, n4=idx>>5;
            float4 v=*(const float4*)&O[(tk+k)*256 + d0+n4*4];
            Bs[(n4*4  )*36+k]=tf32cvt(v.x);
            Bs[(n4*4+1)*36+k]=tf32cvt(v.y);
            Bs[(n4*4+2)*36+k]=tf32cvt(v.z);
            Bs[(n4*4+3)*36+k]=tf32cvt(v.w);
        }
        __syncthreads();
        #pragma unroll
        for (int ks=0;ks<4;ks++){
            int ko=ks*8;
            unsigned int a0=As[(wm*16+g)*36+ko+tg],   a1=As[(wm*16+g+8)*36+ko+tg];
            unsigned int a2=As[(wm*16+g)*36+ko+tg+4], a3=As[(wm*16+g+8)*36+ko+tg+4];
            #pragma unroll
            for (int nt=0;nt<4;nt++){
                int no=wn*32+nt*8;
                unsigned int b0=Bs[(no+g)*36+ko+tg], b1=Bs[(no+g)*36+ko+tg+4];
                mma8(acc[nt], a0,a1,a2,a3,b0,b1);
            }
        }
        __syncthreads();
    }
    float* A=g_att+(size_t)b*Tt*256;
    int i_a = i0 + wm*16 + g, i_b = i_a + 8;
    #pragma unroll
    for (int nt=0;nt<4;nt++){
        int col = d0 + wn*32 + nt*8 + tg*2;
        float2 r0; r0.x=acc[nt][0]; r0.y=acc[nt][1];
        float2 r1; r1.x=acc[nt][2]; r1.y=acc[nt][3];
        *(float2*)&A[(size_t)i_a*256+col]=r0;
        *(float2*)&A[(size_t)i_b*256+col]=r1;
    }
}

// ------------- full attention: scores + softmax over batch (per t) -------------
__global__ void k_score(int layer){
    const float* O = layer? g_out2 : g_out1;
    const float* h = g_h[layer];
    int t=blockIdx.x, tid=threadIdx.x, w=tid>>5, lane=tid&31;
    __shared__ float sc[64];
    for (int j=0;j<8;j++){
        int b=w*8+j;
        const float* o=O+((size_t)b*Tt+t)*256;
        const float* hb=h+b*256;
        float a=0.f;
        for (int k=lane;k<256;k+=32) a=fmaf(o[k],hb[k],a);
        a=wsum(a);
        if (lane==0) sc[b]=a*(1.f/512.f);
    }
    __syncthreads();
    if (tid<32){
        float v0=sc[tid], v1=sc[tid+32];
        float m=fmaxf(v0,v1);
        #pragma unroll
        for (int o=16;o;o>>=1) m=fmaxf(m,__shfl_xor_sync(0xffffffffu,m,o));
        float e0=__expf(v0-m), e1=__expf(v1-m);
        float s=e0+e1;
        s=wsum(s);
        float inv=__fdividef(1.f,s);
        g_sc[t*64+tid]=e0*inv;
        g_sc[t*64+tid+32]=e1*inv;
    }
}

__global__ void k_fsum1(int layer){
    const float* O = layer? g_out2 : g_out1;
    int b=blockIdx.x, tc=blockIdx.y, d=threadIdx.x;
    const float* o=O+(size_t)b*Tt*256;
    float a=0.f;
    int t0=tc*64;
    for (int t=t0;t<t0+64;t++) a=fmaf(g_sc[t*64+b], o[t*256+d], a);
    g_part[b][tc][d]=a;
}
__global__ void k_fsum2(int layer){
    int b=blockIdx.x, d=threadIdx.x;
    float a=0.f;
    #pragma unroll
    for (int c=0;c<8;c++) a+=g_part[b][c][d];
    if (layer==0) g_att[((size_t)b*Tt+511)*256+d]=a;
    else          g_a2[b*256+d]=a;
}

// ------------- layer-2 input projection GEMM: xg2 = att @ Wih2^T + bias, tf32 mma -------------
__global__ __launch_bounds__(256) void k_xg2(
    const float* __restrict__ Wf, const float* __restrict__ bf1, const float* __restrict__ bf2,
    const float* __restrict__ Wb, const float* __restrict__ bb1, const float* __restrict__ bb2)
{
    int t0=blockIdx.x*64, col0=blockIdx.y*64;
    int z=blockIdx.z; int b=z>>1, dir=z&1;
    const float* W2 = dir? Wb : Wf;
    __shared__ unsigned int As[64*36], Bs[64*36];
    __shared__ float bsh[64];
    int tid=threadIdx.x;
    int lane=tid&31, wid=tid>>5, g=lane>>2, tg=lane&3;
    int wm=wid>>1, wn=wid&1;
    if (tid<64) bsh[tid] = dir? (bb1[col0+tid]+bb2[col0+tid]) : (bf1[col0+tid]+bf2[col0+tid]);
    const float* A = g_att + (size_t)b*Tt*256;
    float acc[4][4]={};
    for (int kc=0;kc<256;kc+=32){
        #pragma unroll
        for (int e=0;e<2;e++){
            int idx=tid+e*256; int m=idx>>3, k4=idx&7;
            float4 va=*(const float4*)&A[(t0+m)*256+kc+k4*4];
            float4 vb=*(const float4*)&W2[(col0+m)*256+kc+k4*4];
            int base=m*36+k4*4;
            As[base]=tf32cvt(va.x); As[base+1]=tf32cvt(va.y); As[base+2]=tf32cvt(va.z); As[base+3]=tf32cvt(va.w);
            Bs[base]=tf32cvt(vb.x); Bs[base+1]=tf32cvt(vb.y); Bs[base+2]=tf32cvt(vb.z); Bs[base+3]=tf32cvt(vb.w);
        }
        __syncthreads();
        #pragma unroll
        for (int ks=0;ks<4;ks++){
            int ko=ks*8;
            unsigned int a0=As[(wm*16+g)*36+ko+tg],   a1=As[(wm*16+g+8)*36+ko+tg];
            unsigned int a2=As[(wm*16+g)*36+ko+tg+4], a3=As[(wm*16+g+8)*36+ko+tg+4];
            #pragma unroll
            for (int nt=0;nt<4;nt++){
                int no=wn*32+nt*8;
                unsigned int b0=Bs[(no+g)*36+ko+tg], b1=Bs[(no+g)*36+ko+tg+4];
                mma8(acc[nt], a0,a1,a2,a3,b0,b1);
            }
        }
        __syncthreads();
    }
    int t_a = t0 + wm*16 + g, t_b = t_a + 8;
    #pragma unroll
    for (int nt=0;nt<4;nt++){
        int cl = wn*32 + nt*8 + tg*2;
        float2 r0; r0.x=acc[nt][0]+bsh[cl]; r0.y=acc[nt][1]+bsh[cl+1];
        float2 r1; r1.x=acc[nt][2]+bsh[cl]; r1.y=acc[nt][3]+bsh[cl+1];
        *(float2*)&g_xg[dir][(t_a*Bb+b)*512 + col0 + cl] = r0;
        *(float2*)&g_xg[dir][(t_b*Bb+b)*512 + col0 + cl] = r1;
    }
}

__global__ void k_final(const float* __restrict__ W, const float* __restrict__ bb, float* out){
    __shared__ float w[256];
    int tid=threadIdx.x;
    for (int i=tid;i<256;i+=64) w[i]=W[i];
    __syncthreads();
    float a=bb[0];
    for (int k=0;k<256;k++) a=fmaf(g_a2[tid*256+k],w[k],a);
    out[tid]=sigm_fast(a);
}

extern "C" void kernel_launch(void* const* d_in, const int* in_sizes, int n_in,
                              void* d_out, int out_size)
{
    const int*   x   = (const int*)  d_in[0];
    const float* emb = (const float*)d_in[1];
    const float* l1Wihf=(const float*)d_in[2],  *l1Whhf=(const float*)d_in[3];
    const float* l1bihf=(const float*)d_in[4],  *l1bhhf=(const float*)d_in[5];
    const float* l1Wihb=(const float*)d_in[6],  *l1Whhb=(const float*)d_in[7];
    const float* l1bihb=(const float*)d_in[8],  *l1bhhb=(const float*)d_in[9];
    const float* l2Wihf=(const float*)d_in[10], *l2Whhf=(const float*)d_in[11];
    const float* l2bihf=(const float*)d_in[12], *l2bhhf=(const float*)d_in[13];
    const float* l2Wihb=(const float*)d_in[14], *l2Whhb=(const float*)d_in[15];
    const float* l2bihb=(const float*)d_in[16], *l2bhhb=(const float*)d_in[17];
    const float* linW=(const float*)d_in[18],   *linb=(const float*)d_in[19];
    float* out=(float*)d_out;

    k_xg1<<<dim3(8,64),256>>>(x,emb,l1Wihf,l1bihf,l1bhhf,l1Wihb,l1bihb,l1bhhb);
    k_rec<<<128,256>>>(0,l1Whhf,l1Whhb);
    k_gram<<<dim3(8,8,64),256>>>();
    k_bsoft<<<512,512>>>();
    k_apply<<<dim3(8,4,64),256>>>();
    k_score<<<512,256>>>(0);
    k_fsum1<<<dim3(64,8),256>>>(0);
    k_fsum2<<<64,256>>>(0);
    k_xg2<<<dim3(8,8,128),256>>>(l2Wihf,l2bihf,l2bhhf,l2Wihb,l2bihb,l2bhhb);
    k_rec<<<128,256>>>(1,l2Whhf,l2Whhb);
    k_score<<<512,256>>>(1);
    k_fsum1<<<dim3(64,8),256>>>(1);
    k_fsum2<<<64,256>>>(1);
    k_final<<<1,64>>>(linW,linb,out);
}

// round 16
// speedup vs baseline: 1.3698x; 1.2494x over previous
#include <cuda_runtime.h>
#include <stdint.h>
#include <math.h>

#define Tt 512
#define Bb 64

// ------------- static device scratch -------------
__device__ float g_xg[2][Tt*Bb*512];      // [dir][(t*64+b)*512+col]
__device__ float g_out1[Bb*Tt*256];
__device__ float g_out2[Bb*Tt*256];
__device__ float g_att[Bb*Tt*256];
__device__ float g_S[(size_t)Bb*Tt*Tt];   // gram -> softmaxed weights in place
__device__ float g_h[2][2*Bb*128];
__device__ float g_sc[Tt*Bb];
__device__ float g_a2[Bb*256];
__device__ float g_part[Bb][8][256];

__device__ __forceinline__ float sigm_fast(float x){ return __fdividef(1.f, 1.f + __expf(-x)); }
__device__ __forceinline__ float tanh_fast(float x){ return 1.f - __fdividef(2.f, __expf(2.f*x) + 1.f); }
__device__ __forceinline__ float wsum(float v){
    #pragma unroll
    for (int o=16;o;o>>=1) v += __shfl_xor_sync(0xffffffffu, v, o);
    return v;
}
__device__ __forceinline__ void fma2(unsigned long long &acc, unsigned long long a, unsigned long long b){
    asm("fma.rn.f32x2 %0, %1, %2, %0;" : "+l"(acc) : "l"(a), "l"(b));
}
__device__ __forceinline__ unsigned int tf32cvt(float x){
    unsigned int u; asm("cvt.rna.tf32.f32 %0, %1;" : "=r"(u) : "f"(x)); return u;
}
__device__ __forceinline__ void mma8(float* c, unsigned int a0,unsigned int a1,unsigned int a2,unsigned int a3,
                                     unsigned int b0,unsigned int b1){
    asm volatile("mma.sync.aligned.m16n8k8.row.col.f32.tf32.tf32.f32 "
        "{%0,%1,%2,%3}, {%4,%5,%6,%7}, {%8,%9}, {%0,%1,%2,%3};"
        : "+f"(c[0]),"+f"(c[1]),"+f"(c[2]),"+f"(c[3])
        : "r"(a0),"r"(a1),"r"(a2),"r"(a3),"r"(b0),"r"(b1));
}

// ------------- layer-1 input projection (embedding fused), both dirs -------------
__global__ __launch_bounds__(256) void k_xg1(
    const int* __restrict__ x, const float* __restrict__ emb,
    const float* __restrict__ Wf, const float* __restrict__ bf1, const float* __restrict__ bf2,
    const float* __restrict__ Wb, const float* __restrict__ bb1, const float* __restrict__ bb2)
{
    __shared__ float wf[5120], wb[5120], bf[512], bb[512], e[10];
    int b = blockIdx.y, t0 = blockIdx.x*64, tid = threadIdx.x;
    for (int i=tid;i<5120;i+=256){ wf[i]=Wf[i]; wb[i]=Wb[i]; }
    for (int i=tid;i<512;i+=256){ bf[i]=bf1[i]+bf2[i]; bb[i]=bb1[i]+bb2[i]; }
    __syncthreads();
    for (int tl=0; tl<64; tl++){
        int t = t0+tl;
        if (tid<10) e[tid] = emb[x[b*Tt+t]*10+tid];
        __syncthreads();
        float ev[10];
        #pragma unroll
        for (int d=0;d<10;d++) ev[d]=e[d];
        for (int c=tid;c<512;c+=256){
            float af=bf[c], ab=bb[c];
            #pragma unroll
            for (int d=0;d<10;d++){ af=fmaf(ev[d],wf[c*10+d],af); ab=fmaf(ev[d],wb[c*10+d],ab); }
            g_xg[0][(t*Bb+b)*512+c]=af;
            g_xg[1][(t*Bb+b)*512+c]=ab;
        }
        __syncthreads();
    }
}

// ------------- persistent bidirectional LSTM recurrence, cluster-of-2 -------------
// R11 structure (count=256 mbarrier: 128 peer cluster-arrivals + 128 local
// arrivals; wait immediately after cell phase; no extra syncthreads/fences).
// New: gate activations applied in the 256-thread gate phase (warp-uniform
// branch), and the DSMEM store + arrives precede the global out STG.
__global__ __launch_bounds__(256,1) __cluster_dims__(2,1,1)
void k_rec(int layer, const float* __restrict__ Whh_f, const float* __restrict__ Whh_b)
{
    __shared__ __align__(16) float hsh[2][2][128];   // [phase][batch][j]
    __shared__ float gsh[2][256];                    // [batch][g*64+kl] (pre-activated)
    __shared__ __align__(8) unsigned long long mbar[2];
    int cid = blockIdx.x>>1;
    unsigned int rank; asm("mov.u32 %0, %%cluster_ctarank;" : "=r"(rank));
    int dir = cid>>5, bpair = cid&31;
    int kb = (int)rank*64;
    int b0 = bpair*2;
    const float* Whh = dir? Whh_b : Whh_f;
    const float* xg  = g_xg[dir];
    float* out = layer? g_out2 : g_out1;
    int tid = threadIdx.x;
    int g = tid>>6, kl = tid&63;
    int grow = g*128 + kb + kl;

    unsigned long long wp[64];
    {
        const float4* wr = (const float4*)&Whh[grow*128];
        #pragma unroll
        for (int i=0;i<32;i++){
            float4 w = __ldg(&wr[i]);
            asm("mov.b64 %0, {%1,%2};" : "=l"(wp[2*i])   : "f"(w.x), "f"(w.y));
            asm("mov.b64 %0, {%1,%2};" : "=l"(wp[2*i+1]) : "f"(w.z), "f"(w.w));
        }
    }
    for (int i=tid;i<512;i+=256) ((float*)hsh)[i]=0.f;

    int cbl = tid>>6, ckl = tid&63;
    float cst = 0.f;

    unsigned int hbase;
    asm("{ .reg .u64 t; cvta.to.shared.u64 t, %1; cvt.u32.u64 %0, t; }" : "=r"(hbase) : "l"((void*)hsh));
    unsigned int mbase;
    asm("{ .reg .u64 t; cvta.to.shared.u64 t, %1; cvt.u32.u64 %0, t; }" : "=r"(mbase) : "l"((void*)mbar));
    if (tid==0){
        asm volatile("mbarrier.init.shared.b64 [%0], %1;" :: "r"(mbase),   "r"(256u) : "memory");
        asm volatile("mbarrier.init.shared.b64 [%0], %1;" :: "r"(mbase+8), "r"(256u) : "memory");
    }
    unsigned int peer_hbase, peer_mbase;
    asm("mapa.shared::cluster.u32 %0, %1, %2;" : "=r"(peer_hbase) : "r"(hbase), "r"(rank^1u));
    asm("mapa.shared::cluster.u32 %0, %1, %2;" : "=r"(peer_mbase) : "r"(mbase), "r"(rank^1u));

    __syncthreads();
    asm volatile("barrier.cluster.arrive.aligned;" ::: "memory");
    asm volatile("barrier.cluster.wait.aligned;"   ::: "memory");

    int tI = dir? 511 : 0;
    float xgc0 = __ldg(&xg[(tI*Bb + b0  )*512 + grow]);
    float xgc1 = __ldg(&xg[(tI*Bb + b0+1)*512 + grow]);
    int p = 0;
    int par0 = 0, par1 = 0;

    for (int s=0; s<Tt; s++){
        int t = dir ? (511-s) : s;
        unsigned long long a0e=0ull, a0o=0ull, a1e=0ull, a1o=0ull;
        const ulonglong2* h0p = (const ulonglong2*)hsh[p][0];
        const ulonglong2* h1p = (const ulonglong2*)hsh[p][1];
        #pragma unroll
        for (int i=0;i<32;i++){
            ulonglong2 ha = h0p[i], hb = h1p[i];
            fma2(a0e, wp[2*i],   ha.x);
            fma2(a0o, wp[2*i+1], ha.y);
            fma2(a1e, wp[2*i],   hb.x);
            fma2(a1o, wp[2*i+1], hb.y);
        }
        float u0,v0,u1,v1,u2,v2,u3,v3;
        asm("mov.b64 {%0,%1}, %2;" : "=f"(u0),"=f"(v0) : "l"(a0e));
        asm("mov.b64 {%0,%1}, %2;" : "=f"(u1),"=f"(v1) : "l"(a0o));
        asm("mov.b64 {%0,%1}, %2;" : "=f"(u2),"=f"(v2) : "l"(a1e));
        asm("mov.b64 {%0,%1}, %2;" : "=f"(u3),"=f"(v3) : "l"(a1o));
        float s0 = (u0+v0) + (u1+v1) + xgc0;
        float s1 = (u2+v2) + (u3+v3) + xgc1;
        // pre-activate: gate index g is warp-uniform (tid>>6)
        if (g==2){ s0 = tanh_fast(s0); s1 = tanh_fast(s1); }
        else     { s0 = sigm_fast(s0); s1 = sigm_fast(s1); }
        gsh[0][tid] = s0;
        gsh[1][tid] = s1;
        if (s<511){
            int tn = dir? (510-s) : (s+1);
            xgc0 = __ldg(&xg[(tn*Bb + b0  )*512 + grow]);
            xgc1 = __ldg(&xg[(tn*Bb + b0+1)*512 + grow]);
        }
        __syncthreads();
        int np = p^1;
        if (tid<128){
            float gi=gsh[cbl][ckl], gf=gsh[cbl][64+ckl], gg=gsh[cbl][128+ckl], go=gsh[cbl][192+ckl];
            cst = gf*cst + gi*gg;
            float hv = go*tanh_fast(cst);
            int k = kb + ckl;
            if (s==511){
                out[((b0+cbl)*Tt + t)*256 + dir*128 + k] = hv;
                g_h[layer][dir*Bb*128 + (b0+cbl)*128 + k] = hv;
            } else {
                hsh[np][cbl][k] = hv;
                unsigned int off = (unsigned int)(((np*2+cbl)*128 + k)*4);
                asm volatile("st.shared::cluster.f32 [%0], %1;" :: "r"(peer_hbase+off), "f"(hv) : "memory");
                asm volatile("mbarrier.arrive.shared::cluster.b64 _, [%0];" :: "r"(peer_mbase + (unsigned)np*8u) : "memory");
                asm volatile("mbarrier.arrive.shared.b64 _, [%0];" :: "r"(mbase + (unsigned)np*8u) : "memory");
                out[((b0+cbl)*Tt + t)*256 + dir*128 + k] = hv;
            }
        }
        if (s<511){
            int ph = np ? par1 : par0;
            unsigned int mbaddr = mbase + (unsigned)np*8u;
            unsigned int done;
            asm volatile(
                "{\n\t.reg .pred p;\n\t"
                "mbarrier.try_wait.parity.acquire.cluster.shared::cta.b64 p, [%1], %2;\n\t"
                "selp.b32 %0, 1, 0, p;\n\t}"
                : "=r"(done) : "r"(mbaddr), "r"((unsigned)ph) : "memory");
            while (!done){
                asm volatile(
                    "{\n\t.reg .pred p;\n\t"
                    "mbarrier.try_wait.parity.acquire.cluster.shared::cta.b64 p, [%1], %2, 0x989680;\n\t"
                    "selp.b32 %0, 1, 0, p;\n\t}"
                    : "=r"(done) : "r"(mbaddr), "r"((unsigned)ph) : "memory");
            }
            if (np) par1^=1; else par0^=1;
        }
        p ^= 1;
    }
    asm volatile("barrier.cluster.arrive.aligned;" ::: "memory");
    asm volatile("barrier.cluster.wait.aligned;"   ::: "memory");
}

// ------------- prefix gram S[b][i][t]=dot/max(i,1), tf32 mma, 64x64 tiles -------------
__global__ __launch_bounds__(256) void k_gram(){
    int ti=blockIdx.x, tj=blockIdx.y, b=blockIdx.z;
    if (tj>ti) return;
    __shared__ unsigned int As[64*36], Bs[64*36];
    const float* O = g_out1 + (size_t)b*Tt*256;
    int i0=ti*64, t0=tj*64, tid=threadIdx.x;
    int lane=tid&31, wid=tid>>5, g=lane>>2, tg=lane&3;
    int wm=wid>>1, wn=wid&1;
    float acc[4][4]={};
    for (int kc=0;kc<256;kc+=32){
        #pragma unroll
        for (int e=0;e<2;e++){
            int idx=tid+e*256; int m=idx>>3, k4=idx&7;
            float4 va=*(const float4*)&O[(i0+m)*256+kc+k4*4];
            float4 vb=*(const float4*)&O[(t0+m)*256+kc+k4*4];
            int base=m*36+k4*4;
            As[base]=tf32cvt(va.x); As[base+1]=tf32cvt(va.y); As[base+2]=tf32cvt(va.z); As[base+3]=tf32cvt(va.w);
            Bs[base]=tf32cvt(vb.x); Bs[base+1]=tf32cvt(vb.y); Bs[base+2]=tf32cvt(vb.z); Bs[base+3]=tf32cvt(vb.w);
        }
        __syncthreads();
        #pragma unroll
        for (int ks=0;ks<4;ks++){
            int ko=ks*8;
            unsigned int a0=As[(wm*16+g)*36+ko+tg],   a1=As[(wm*16+g+8)*36+ko+tg];
            unsigned int a2=As[(wm*16+g)*36+ko+tg+4], a3=As[(wm*16+g+8)*36+ko+tg+4];
            #pragma unroll
            for (int nt=0;nt<4;nt++){
                int no=wn*32+nt*8;
                unsigned int b0=Bs[(no+g)*36+ko+tg], b1=Bs[(no+g)*36+ko+tg+4];
                mma8(acc[nt], a0,a1,a2,a3,b0,b1);
            }
        }
        __syncthreads();
    }
    int i_a = i0 + wm*16 + g, i_b = i_a + 8;
    float sa = 1.f/(float)(i_a>0?i_a:1), sb = 1.f/(float)(i_b>0?i_b:1);
    #pragma unroll
    for (int nt=0;nt<4;nt++){
        int col = t0 + wn*32 + nt*8 + tg*2;
        float2 r0; r0.x=acc[nt][0]*sa; r0.y=acc[nt][1]*sa;
        float2 r1; r1.x=acc[nt][2]*sb; r1.y=acc[nt][3]*sb;
        *(float2*)&g_S[((size_t)b*Tt+i_a)*Tt+col]=r0;
        *(float2*)&g_S[((size_t)b*Tt+i_b)*Tt+col]=r1;
    }
}

// ------------- softmax over batch per (i,t), t<i -------------
__global__ void k_bsoft(){
    int i=blockIdx.x, t=threadIdx.x;
    if (t>=i) return;
    size_t base=(size_t)i*Tt+t;
    float v[64], m=-1e30f;
    #pragma unroll
    for (int b=0;b<64;b++){ v[b]=g_S[(size_t)b*Tt*Tt+base]; m=fmaxf(m,v[b]); }
    float s=0.f;
    #pragma unroll
    for (int b=0;b<64;b++){ v[b]=__expf(v[b]-m); s+=v[b]; }
    float inv=__fdividef(1.f,s);
    #pragma unroll
    for (int b=0;b<64;b++) g_S[(size_t)b*Tt*Tt+base]=v[b]*inv;
}

// ------------- att[b][i][:] = sum_{t<i} W[b,i,t]*out1[b,t,:], tf32 mma -------------
__global__ __launch_bounds__(256) void k_apply(){
    int i0=blockIdx.x*64, d0=blockIdx.y*64, b=blockIdx.z;
    __shared__ unsigned int As[64*36], Bs[64*36];
    const float* O=g_out1+(size_t)b*Tt*256;
    const float* W=g_S+(size_t)b*Tt*Tt;
    int tid=threadIdx.x;
    int lane=tid&31, wid=tid>>5, g=lane>>2, tg=lane&3;
    int wm=wid>>1, wn=wid&1;
    float acc[4][4]={};
    int kmax=i0+64;
    for (int tk=0;tk<kmax;tk+=32){
        #pragma unroll
        for (int e=0;e<2;e++){
            int idx=tid+e*256; int m=idx>>3, k4=idx&7;
            int i_r = i0+m;
            int tbase = tk+k4*4;
            float4 va=*(const float4*)&W[(size_t)i_r*Tt + tbase];
            if (tbase+0 >= i_r) va.x=0.f;
            if (tbase+1 >= i_r) va.y=0.f;
            if (tbase+2 >= i_r) va.z=0.f;
            if (tbase+3 >= i_r) va.w=0.f;
            int base=m*36+k4*4;
            As[base]=tf32cvt(va.x); As[base+1]=tf32cvt(va.y); As[base+2]=tf32cvt(va.z); As[base+3]=tf32cvt(va.w);
        }
        #pragma unroll
        for (int e=0;e<2;e++){
            int idx=tid+e*256; int k=idx&31, n4=idx>>5;
            float4 v=*(const float4*)&O[(tk+k)*256 + d0+n4*4];
            Bs[(n4*4  )*36+k]=tf32cvt(v.x);
            Bs[(n4*4+1)*36+k]=tf32cvt(v.y);
            Bs[(n4*4+2)*36+k]=tf32cvt(v.z);
            Bs[(n4*4+3)*36+k]=tf32cvt(v.w);
        }
        __syncthreads();
        #pragma unroll
        for (int ks=0;ks<4;ks++){
            int ko=ks*8;
            unsigned int a0=As[(wm*16+g)*36+ko+tg],   a1=As[(wm*16+g+8)*36+ko+tg];
            unsigned int a2=As[(wm*16+g)*36+ko+tg+4], a3=As[(wm*16+g+8)*36+ko+tg+4];
            #pragma unroll
            for (int nt=0;nt<4;nt++){
                int no=wn*32+nt*8;
                unsigned int b0=Bs[(no+g)*36+ko+tg], b1=Bs[(no+g)*36+ko+tg+4];
                mma8(acc[nt], a0,a1,a2,a3,b0,b1);
            }
        }
        __syncthreads();
    }
    float* A=g_att+(size_t)b*Tt*256;
    int i_a = i0 + wm*16 + g, i_b = i_a + 8;
    #pragma unroll
    for (int nt=0;nt<4;nt++){
        int col = d0 + wn*32 + nt*8 + tg*2;
        float2 r0; r0.x=acc[nt][0]; r0.y=acc[nt][1];
        float2 r1; r1.x=acc[nt][2]; r1.y=acc[nt][3];
        *(float2*)&A[(size_t)i_a*256+col]=r0;
        *(float2*)&A[(size_t)i_b*256+col]=r1;
    }
}

// ------------- full attention: scores + softmax over batch (per t) -------------
__global__ void k_score(int layer){
    const float* O = layer? g_out2 : g_out1;
    const float* h = g_h[layer];
    int t=blockIdx.x, tid=threadIdx.x, w=tid>>5, lane=tid&31;
    __shared__ float sc[64];
    for (int j=0;j<8;j++){
        int b=w*8+j;
        const float* o=O+((size_t)b*Tt+t)*256;
        const float* hb=h+b*256;
        float a=0.f;
        for (int k=lane;k<256;k+=32) a=fmaf(o[k],hb[k],a);
        a=wsum(a);
        if (lane==0) sc[b]=a*(1.f/512.f);
    }
    __syncthreads();
    if (tid<32){
        float v0=sc[tid], v1=sc[tid+32];
        float m=fmaxf(v0,v1);
        #pragma unroll
        for (int o=16;o;o>>=1) m=fmaxf(m,__shfl_xor_sync(0xffffffffu,m,o));
        float e0=__expf(v0-m), e1=__expf(v1-m);
        float s=e0+e1;
        s=wsum(s);
        float inv=__fdividef(1.f,s);
        g_sc[t*64+tid]=e0*inv;
        g_sc[t*64+tid+32]=e1*inv;
    }
}

__global__ void k_fsum1(int layer){
    const float* O = layer? g_out2 : g_out1;
    int b=blockIdx.x, tc=blockIdx.y, d=threadIdx.x;
    const float* o=O+(size_t)b*Tt*256;
    float a=0.f;
    int t0=tc*64;
    for (int t=t0;t<t0+64;t++) a=fmaf(g_sc[t*64+b], o[t*256+d], a);
    g_part[b][tc][d]=a;
}
__global__ void k_fsum2(int layer){
    int b=blockIdx.x, d=threadIdx.x;
    float a=0.f;
    #pragma unroll
    for (int c=0;c<8;c++) a+=g_part[b][c][d];
    if (layer==0) g_att[((size_t)b*Tt+511)*256+d]=a;
    else          g_a2[b*256+d]=a;
}

// ------------- layer-2 input projection GEMM: xg2 = att @ Wih2^T + bias, tf32 mma -------------
__global__ __launch_bounds__(256) void k_xg2(
    const float* __restrict__ Wf, const float* __restrict__ bf1, const float* __restrict__ bf2,
    const float* __restrict__ Wb, const float* __restrict__ bb1, const float* __restrict__ bb2)
{
    int t0=blockIdx.x*64, col0=blockIdx.y*64;
    int z=blockIdx.z; int b=z>>1, dir=z&1;
    const float* W2 = dir? Wb : Wf;
    __shared__ unsigned int As[64*36], Bs[64*36];
    __shared__ float bsh[64];
    int tid=threadIdx.x;
    int lane=tid&31, wid=tid>>5, g=lane>>2, tg=lane&3;
    int wm=wid>>1, wn=wid&1;
    if (tid<64) bsh[tid] = dir? (bb1[col0+tid]+bb2[col0+tid]) : (bf1[col0+tid]+bf2[col0+tid]);
    const float* A = g_att + (size_t)b*Tt*256;
    float acc[4][4]={};
    for (int kc=0;kc<256;kc+=32){
        #pragma unroll
        for (int e=0;e<2;e++){
            int idx=tid+e*256; int m=idx>>3, k4=idx&7;
            float4 va=*(const float4*)&A[(t0+m)*256+kc+k4*4];
            float4 vb=*(const float4*)&W2[(col0+m)*256+kc+k4*4];
            int base=m*36+k4*4;
            As[base]=tf32cvt(va.x); As[base+1]=tf32cvt(va.y); As[base+2]=tf32cvt(va.z); As[base+3]=tf32cvt(va.w);
            Bs[base]=tf32cvt(vb.x); Bs[base+1]=tf32cvt(vb.y); Bs[base+2]=tf32cvt(vb.z); Bs[base+3]=tf32cvt(vb.w);
        }
        __syncthreads();
        #pragma unroll
        for (int ks=0;ks<4;ks++){
            int ko=ks*8;
            unsigned int a0=As[(wm*16+g)*36+ko+tg],   a1=As[(wm*16+g+8)*36+ko+tg];
            unsigned int a2=As[(wm*16+g)*36+ko+tg+4], a3=As[(wm*16+g+8)*36+ko+tg+4];
            #pragma unroll
            for (int nt=0;nt<4;nt++){
                int no=wn*32+nt*8;
                unsigned int b0=Bs[(no+g)*36+ko+tg], b1=Bs[(no+g)*36+ko+tg+4];
                mma8(acc[nt], a0,a1,a2,a3,b0,b1);
            }
        }
        __syncthreads();
    }
    int t_a = t0 + wm*16 + g, t_b = t_a + 8;
    #pragma unroll
    for (int nt=0;nt<4;nt++){
        int cl = wn*32 + nt*8 + tg*2;
        float2 r0; r0.x=acc[nt][0]+bsh[cl]; r0.y=acc[nt][1]+bsh[cl+1];
        float2 r1; r1.x=acc[nt][2]+bsh[cl]; r1.y=acc[nt][3]+bsh[cl+1];
        *(float2*)&g_xg[dir][(t_a*Bb+b)*512 + col0 + cl] = r0;
        *(float2*)&g_xg[dir][(t_b*Bb+b)*512 + col0 + cl] = r1;
    }
}

__global__ void k_final(const float* __restrict__ W, const float* __restrict__ bb, float* out){
    __shared__ float w[256];
    int tid=threadIdx.x;
    for (int i=tid;i<256;i+=64) w[i]=W[i];
    __syncthreads();
    float a=bb[0];
    for (int k=0;k<256;k++) a=fmaf(g_a2[tid*256+k],w[k],a);
    out[tid]=sigm_fast(a);
}

extern "C" void kernel_launch(void* const* d_in, const int* in_sizes, int n_in,
                              void* d_out, int out_size)
{
    const int*   x   = (const int*)  d_in[0];
    const float* emb = (const float*)d_in[1];
    const float* l1Wihf=(const float*)d_in[2],  *l1Whhf=(const float*)d_in[3];
    const float* l1bihf=(const float*)d_in[4],  *l1bhhf=(const float*)d_in[5];
    const float* l1Wihb=(const float*)d_in[6],  *l1Whhb=(const float*)d_in[7];
    const float* l1bihb=(const float*)d_in[8],  *l1bhhb=(const float*)d_in[9];
    const float* l2Wihf=(const float*)d_in[10], *l2Whhf=(const float*)d_in[11];
    const float* l2bihf=(const float*)d_in[12], *l2bhhf=(const float*)d_in[13];
    const float* l2Wihb=(const float*)d_in[14], *l2Whhb=(const float*)d_in[15];
    const float* l2bihb=(const float*)d_in[16], *l2bhhb=(const float*)d_in[17];
    const float* linW=(const float*)d_in[18],   *linb=(const float*)d_in[19];
    float* out=(float*)d_out;

    k_xg1<<<dim3(8,64),256>>>(x,emb,l1Wihf,l1bihf,l1bhhf,l1Wihb,l1bihb,l1bhhb);
    k_rec<<<128,256>>>(0,l1Whhf,l1Whhb);
    k_gram<<<dim3(8,8,64),256>>>();
    k_bsoft<<<512,512>>>();
    k_apply<<<dim3(8,4,64),256>>>();
    k_score<<<512,256>>>(0);
    k_fsum1<<<dim3(64,8),256>>>(0);
    k_fsum2<<<64,256>>>(0);
    k_xg2<<<dim3(8,8,128),256>>>(l2Wihf,l2bihf,l2bhhf,l2Wihb,l2bihb,l2bhhb);
    k_rec<<<128,256>>>(1,l2Whhf,l2Whhb);
    k_score<<<512,256>>>(1);
    k_fsum1<<<dim3(64,8),256>>>(1);
    k_fsum2<<<64,256>>>(1);
    k_final<<<1,64>>>(linW,linb,out);
}